// round 4
// baseline (speedup 1.0000x reference)
#include <cuda_runtime.h>

// out[b,k] = tanh( sum_n W[k,n] * x[b,k,n] )
// B=64, K=4096, N=256 (fp32). 262144 rows of 1KB.
//
// R1-R3 all pinned at 6.4-6.5 TB/s DRAM regardless of structure. This variant
// tests the last remaining lever: per-SM DRAM stream sequentiality. Each CTA
// owns a CONTIGUOUS 128-row (128KB) chunk of x; its 8 warps interleave rows
// within the chunk, 2 rows in flight per warp. Per-SM working set is ~2MB
// contiguous (also fixes TLB reach: 268MB total > 256MB TLB span).
// W rows come through L2 (__ldg, L2 has ~50% headroom); x streams with .cs.

#define GN 256
#define GK_MASK 4095          // K = 4096
#define ROWS_PER_CTA 128
#define NUM_CTAS 2048         // 262144 / 128

__global__ __launch_bounds__(256, 5)
void ginn_stream_kernel(const float* __restrict__ x,
                        const float* __restrict__ W,
                        float* __restrict__ out,
                        int total_rows) {
    const int lane = threadIdx.x & 31;
    const int wid  = threadIdx.x >> 5;            // 0..7
    const int base = blockIdx.x * ROWS_PER_CTA;

    const float4* __restrict__ x4 = reinterpret_cast<const float4*>(x);
    const float4* __restrict__ w4 = reinterpret_cast<const float4*>(W);

    // Each warp: rows base+wid, base+wid+8, ... (16 rows), unrolled by 2.
    #pragma unroll 1
    for (int r = base + wid; r < base + ROWS_PER_CTA; r += 16) {
        const int r0 = r;
        const int r1 = r + 8;

        const float4* xp0 = x4 + (size_t)r0 * (GN / 4);
        const float4* xp1 = x4 + (size_t)r1 * (GN / 4);
        const float4* wp0 = w4 + (size_t)(r0 & GK_MASK) * (GN / 4);
        const float4* wp1 = w4 + (size_t)(r1 & GK_MASK) * (GN / 4);

        // Front-batch 8 x-loads (streaming) + 4 W-loads (L2-cached).
        float4 a0 = __ldcs(xp0 + lane);
        float4 c0 = __ldcs(xp0 + lane + 32);
        float4 a1 = __ldcs(xp1 + lane);
        float4 c1 = __ldcs(xp1 + lane + 32);
        float4 u0 = __ldg(wp0 + lane);
        float4 v0 = __ldg(wp0 + lane + 32);
        float4 u1 = __ldg(wp1 + lane);
        float4 v1 = __ldg(wp1 + lane + 32);

        float s0 = a0.x * u0.x;
        s0 = fmaf(a0.y, u0.y, s0); s0 = fmaf(a0.z, u0.z, s0); s0 = fmaf(a0.w, u0.w, s0);
        s0 = fmaf(c0.x, v0.x, s0); s0 = fmaf(c0.y, v0.y, s0);
        s0 = fmaf(c0.z, v0.z, s0); s0 = fmaf(c0.w, v0.w, s0);

        float s1 = a1.x * u1.x;
        s1 = fmaf(a1.y, u1.y, s1); s1 = fmaf(a1.z, u1.z, s1); s1 = fmaf(a1.w, u1.w, s1);
        s1 = fmaf(c1.x, v1.x, s1); s1 = fmaf(c1.y, v1.y, s1);
        s1 = fmaf(c1.z, v1.z, s1); s1 = fmaf(c1.w, v1.w, s1);

        #pragma unroll
        for (int off = 16; off > 0; off >>= 1) {
            s0 += __shfl_xor_sync(0xffffffffu, s0, off);
            s1 += __shfl_xor_sync(0xffffffffu, s1, off);
        }

        if (lane == 0) {
            out[r0] = tanhf(s0);
            out[r1] = tanhf(s1);
        }
    }
}

extern "C" void kernel_launch(void* const* d_in, const int* in_sizes, int n_in,
                              void* d_out, int out_size) {
    const float* x = (const float*)d_in[0];  // [B, K, N] fp32
    const float* W = (const float*)d_in[1];  // [K, N] fp32
    float* out = (float*)d_out;              // [B, K] fp32 (row-major b*K+k)

    const int total_rows = out_size;         // B*K = 262144

    ginn_stream_kernel<<<NUM_CTAS, 256>>>(x, W, out, total_rows);
}

// round 5
// speedup vs baseline: 1.0256x; 1.0256x over previous
#include <cuda_runtime.h>

// out[b,k] = tanh( sum_n W[k,n] * x[b,k,n] )
// B=64, K=4096, N=256 (fp32).
//
// Final form: R1 structure (best measured DRAM%: 82.2%, 6.51 TB/s), minus all
// non-essential overhead. Four structurally diverse variants (R1-R4) all pin
// at 6.4-6.5 TB/s moving exactly the compulsory 276 MB -> this problem is at
// the achieved-HBM wall; only sub-% launch/epilogue costs remain.
//  - exact grid, no bounds guard (B*K = 262144 divisible by warps/block)
//  - out written with .cs (never re-read; don't allocate L2 write sectors
//    against the x fill stream)
//  - W via __ldg (L2-resident, 4 MB)

#define GK 4096
#define GN 256

__global__ __launch_bounds__(256, 8)
void ginn_final_kernel(const float* __restrict__ x,
                       const float* __restrict__ W,
                       float* __restrict__ out) {
    const int warp = (blockIdx.x * blockDim.x + threadIdx.x) >> 5;
    const int lane = threadIdx.x & 31;
    const int k = warp & (GK - 1);

    const float4* __restrict__ xp =
        reinterpret_cast<const float4*>(x + (size_t)warp * GN);
    const float4* __restrict__ wp =
        reinterpret_cast<const float4*>(W + (size_t)k * GN);

    // 256 floats = 64 float4 per row; 32 lanes x 2. Front-batch all 4 loads.
    const float4 x0 = xp[lane];
    const float4 x1 = xp[lane + 32];
    const float4 w0 = __ldg(wp + lane);
    const float4 w1 = __ldg(wp + lane + 32);

    float s = x0.x * w0.x;
    s = fmaf(x0.y, w0.y, s);
    s = fmaf(x0.z, w0.z, s);
    s = fmaf(x0.w, w0.w, s);
    s = fmaf(x1.x, w1.x, s);
    s = fmaf(x1.y, w1.y, s);
    s = fmaf(x1.z, w1.z, s);
    s = fmaf(x1.w, w1.w, s);

    #pragma unroll
    for (int off = 16; off > 0; off >>= 1)
        s += __shfl_xor_sync(0xffffffffu, s, off);

    if (lane == 0)
        __stcs(out + warp, tanhf(s));
}

extern "C" void kernel_launch(void* const* d_in, const int* in_sizes, int n_in,
                              void* d_out, int out_size) {
    const float* x = (const float*)d_in[0];  // [B, K, N] fp32
    const float* W = (const float*)d_in[1];  // [K, N] fp32
    float* out = (float*)d_out;              // [B, K] fp32

    const int total_outputs = out_size;      // 262144, divisible by 8
    const int threads = 256;                 // 8 warps/block
    const int blocks = total_outputs / (threads / 32);  // 32768, exact

    ginn_final_kernel<<<blocks, threads>>>(x, W, out);
}